// round 1
// baseline (speedup 1.0000x reference)
#include <cuda_runtime.h>
#include <math.h>

#define NF   512          // frames
#define TOK  196          // tokens per frame
#define EMB  2560         // embed dim
#define HID  512          // hidden dim
#define E4   (EMB/4)      // 640 float4 per row
#define NCOL (HID + NF)   // 1024 columns of fused GEMM output

// ---------------- scratch (device globals; no allocation allowed) ----------
__device__ float    g_pooled[NF * EMB];     // pooled -> layernormed in place
__device__ float    g_pooledT[EMB * NF];    // transpose for GEMM B operand
__device__ float    g_txt[EMB];             // layernormed text
__device__ float    g_inv[NF];              // 1 / max(||pooled_ln row||, 1e-8)
__device__ float    g_tvec[HID];            // txt_ln @ W1_top
__device__ float    g_E[NF * NCOL];         // [pooled_ln@W1_bot | pooled_ln@pooled_ln^T]
__device__ float    g_gates[NF];
__device__ unsigned g_mask[NF * 16];        // f2f > 0.98 bitmask, 512 bits/row

// ---------------- helpers ---------------------------------------------------
template<int NW>
__device__ __forceinline__ float block_sum(float v, float* sh) {
    #pragma unroll
    for (int o = 16; o > 0; o >>= 1) v += __shfl_down_sync(0xffffffffu, v, o);
    if ((threadIdx.x & 31) == 0) sh[threadIdx.x >> 5] = v;
    __syncthreads();
    float tot = 0.f;
    #pragma unroll
    for (int i = 0; i < NW; i++) tot += sh[i];
    __syncthreads();   // allow sh reuse
    return tot;
}

// ---------------- 1) mean over tokens (HBM-bound, 1.03 GB read) -------------
__global__ void __launch_bounds__(128) k_mean(const float* __restrict__ img) {
    int f  = blockIdx.x;
    int e4 = blockIdx.y * 128 + threadIdx.x;                 // 0..639
    const float4* p = reinterpret_cast<const float4*>(img) + (size_t)f * TOK * E4 + e4;
    float4 a = make_float4(0.f, 0.f, 0.f, 0.f);
    #pragma unroll 4
    for (int t = 0; t < TOK; t++) {
        float4 v = p[(size_t)t * E4];
        a.x += v.x; a.y += v.y; a.z += v.z; a.w += v.w;
    }
    const float s = 1.0f / (float)TOK;
    a.x *= s; a.y *= s; a.z *= s; a.w *= s;
    reinterpret_cast<float4*>(g_pooled)[(size_t)f * E4 + e4] = a;
}

// ---------------- 2) layernorm (frames in-place; block NF handles text) -----
__global__ void __launch_bounds__(256) k_ln(const float* __restrict__ txt,
                                            const float* __restrict__ lng,
                                            const float* __restrict__ lnb,
                                            const float* __restrict__ tg,
                                            const float* __restrict__ tb) {
    __shared__ float sh[8];
    int  bid   = blockIdx.x;
    bool istxt = (bid == NF);
    const float* x   = istxt ? txt : (g_pooled + (size_t)bid * EMB);
    const float* gam = istxt ? tg  : lng;
    const float* bet = istxt ? tb  : lnb;

    float v[10]; float s = 0.f, s2 = 0.f;
    #pragma unroll
    for (int i = 0; i < 10; i++) {
        v[i] = x[threadIdx.x + i * 256];
        s += v[i]; s2 += v[i] * v[i];
    }
    float S  = block_sum<8>(s,  sh);
    float S2 = block_sum<8>(s2, sh);
    float mean = S * (1.0f / EMB);
    float var  = S2 * (1.0f / EMB) - mean * mean;
    float rstd = rsqrtf(var + 1e-5f);

    float n2 = 0.f;
    float* dst = istxt ? g_txt : (g_pooled + (size_t)bid * EMB);
    #pragma unroll
    for (int i = 0; i < 10; i++) {
        int e = threadIdx.x + i * 256;
        float y = (v[i] - mean) * rstd * gam[e] + bet[e];
        dst[e] = y;
        n2 += y * y;
    }
    if (!istxt) {
        float N2 = block_sum<8>(n2, sh);
        if (threadIdx.x == 0) g_inv[bid] = 1.0f / fmaxf(sqrtf(N2), 1e-8f);
    }
}

// ---------------- 3a) transpose pooled_ln -> [EMB, NF] ----------------------
__global__ void __launch_bounds__(256) k_transpose() {
    __shared__ float tile[32][33];
    int x  = blockIdx.x * 32 + threadIdx.x;   // embed col (0..2559)
    int y0 = blockIdx.y * 32;                 // frame row base
    #pragma unroll
    for (int j = threadIdx.y; j < 32; j += 8)
        tile[j][threadIdx.x] = g_pooled[(size_t)(y0 + j) * EMB + x];
    __syncthreads();
    int fo = y0 + threadIdx.x;                // output col (frame)
    int e0 = blockIdx.x * 32;                 // output row base (embed)
    #pragma unroll
    for (int j = threadIdx.y; j < 32; j += 8)
        g_pooledT[(size_t)(e0 + j) * NF + fo] = tile[threadIdx.x][j];
}

// ---------------- 3b) tvec = txt_ln @ W1_top  [HID] -------------------------
__global__ void __launch_bounds__(64) k_tvec(const float* __restrict__ W1) {
    int h = blockIdx.x * 64 + threadIdx.x;
    float s = 0.f;
    #pragma unroll 8
    for (int e = 0; e < EMB; e++) s += g_txt[e] * W1[(size_t)e * HID + h];
    g_tvec[h] = s;
}

// ---------------- 4) fused GEMM  E = A @ [W1_bot | A^T]  (fp32 SIMT) --------
// A = g_pooled [512, 2560] row-major. Both B halves have row stride 512.
#define BM 64
#define BN 64
#define BK 16
__global__ void __launch_bounds__(128) k_gemm(const float* __restrict__ W1) {
    __shared__ float As[BK][BM + 4];   // [k][m], row stride 68 floats (16B aligned)
    __shared__ float Bs[BK][BN];       // [k][n]

    int bn = blockIdx.x * BN;          // 0..960
    int bm = blockIdx.y * BM;          // 0..448
    const float* Bbase = (bn < HID) ? (W1 + (size_t)EMB * HID + bn)
                                    : (g_pooledT + (bn - HID));
    const float* Abase = g_pooled + (size_t)bm * EMB;

    int tid = threadIdx.x;
    int tx  = tid & 15;                // 4 output cols each
    int ty  = tid >> 4;                // 8 output rows each

    float acc[8][4];
    #pragma unroll
    for (int i = 0; i < 8; i++)
        #pragma unroll
        for (int j = 0; j < 4; j++) acc[i][j] = 0.f;

    for (int k0 = 0; k0 < EMB; k0 += BK) {
        // A tile: 64 rows x 16 k, float4 along k, stored transposed
        {
            int c4 = tid & 3;          // k/4
            int r  = tid >> 2;         // 0..31
            #pragma unroll
            for (int i = 0; i < 2; i++) {
                int rr = r + i * 32;
                float4 va = *reinterpret_cast<const float4*>(
                    Abase + (size_t)rr * EMB + k0 + c4 * 4);
                As[c4 * 4 + 0][rr] = va.x;
                As[c4 * 4 + 1][rr] = va.y;
                As[c4 * 4 + 2][rr] = va.z;
                As[c4 * 4 + 3][rr] = va.w;
            }
        }
        // B tile: 16 k-rows x 64 n, float4 along n
        {
            int c4 = tid & 15;         // n/4
            int r  = tid >> 4;         // 0..7
            #pragma unroll
            for (int i = 0; i < 2; i++) {
                int kk = r + i * 8;
                float4 vb = *reinterpret_cast<const float4*>(
                    Bbase + (size_t)(k0 + kk) * 512 + c4 * 4);
                *reinterpret_cast<float4*>(&Bs[kk][c4 * 4]) = vb;
            }
        }
        __syncthreads();
        #pragma unroll
        for (int k = 0; k < BK; k++) {
            float4 a0 = *reinterpret_cast<const float4*>(&As[k][ty * 8]);
            float4 a1 = *reinterpret_cast<const float4*>(&As[k][ty * 8 + 4]);
            float4 b0 = *reinterpret_cast<const float4*>(&Bs[k][tx * 4]);
            float a[8] = {a0.x, a0.y, a0.z, a0.w, a1.x, a1.y, a1.z, a1.w};
            float b[4] = {b0.x, b0.y, b0.z, b0.w};
            #pragma unroll
            for (int i = 0; i < 8; i++)
                #pragma unroll
                for (int j = 0; j < 4; j++)
                    acc[i][j] = fmaf(a[i], b[j], acc[i][j]);
        }
        __syncthreads();
    }
    #pragma unroll
    for (int i = 0; i < 8; i++) {
        float4 o = make_float4(acc[i][0], acc[i][1], acc[i][2], acc[i][3]);
        *reinterpret_cast<float4*>(
            &g_E[(size_t)(bm + ty * 8 + i) * NCOL + bn + tx * 4]) = o;
    }
}

// ---------------- 5) gates + f2f bitmask -------------------------------------
__global__ void __launch_bounds__(128) k_gates(const float* __restrict__ b1,
                                               const float* __restrict__ W2,
                                               const float* __restrict__ b2) {
    __shared__ float sh[4];
    int f   = blockIdx.x;
    int tid = threadIdx.x;

    float s = 0.f;
    #pragma unroll
    for (int h = tid; h < HID; h += 128) {
        float v = g_E[(size_t)f * NCOL + h] + g_tvec[h] + b1[h];
        s += fmaxf(v, 0.f) * W2[h];
    }
    float tot = block_sum<4>(s, sh);
    if (tid == 0) g_gates[f] = 1.0f / (1.0f + expf(-(tot + b2[0])));

    float invi = g_inv[f];
    #pragma unroll
    for (int j = tid; j < NF; j += 128) {
        float c = g_E[(size_t)f * NCOL + HID + j] * invi * g_inv[j];
        unsigned bal = __ballot_sync(0xffffffffu, c > 0.98f);
        if ((j & 31) == 0) g_mask[f * 16 + (j >> 5)] = bal;
    }
}

// ---------------- 6) greedy selection (repeated argmax == sorted scan) ------
__global__ void __launch_bounds__(512) k_select(float* __restrict__ out, int out_size) {
    __shared__ float sg[NF];
    __shared__ int   svis[NF];
    __shared__ int   ssel[NF];
    __shared__ float rk[NF];
    __shared__ int   ri[NF];
    int tid = threadIdx.x;
    sg[tid]  = g_gates[tid];
    svis[tid] = 0;
    ssel[tid] = 0;
    __syncthreads();

    for (int it = 0; it < 32; it++) {
        rk[tid] = svis[tid] ? -1e30f : sg[tid];
        ri[tid] = tid;
        __syncthreads();
        #pragma unroll
        for (int off = 256; off > 0; off >>= 1) {
            if (tid < off) {
                float ko = rk[tid + off]; int io = ri[tid + off];
                // higher gate wins; tie -> lower index (matches stable argsort(-g))
                if (ko > rk[tid] || (ko == rk[tid] && io < ri[tid])) {
                    rk[tid] = ko; ri[tid] = io;
                }
            }
            __syncthreads();
        }
        int   cur  = ri[0];
        float best = rk[0];
        if (best < -1e29f) break;          // everyone visited
        if (tid == 0) ssel[cur] = 1;
        // visited |= (f2f[cur] > thrd); diagonal bit marks cur itself
        unsigned w = g_mask[cur * 16 + (tid >> 5)];
        if (w & (1u << (tid & 31))) svis[tid] = 1;
        __syncthreads();
    }

    if (tid < out_size)        out[tid]      = (float)ssel[tid];
    if (NF + tid < out_size)   out[NF + tid] = sg[tid];
}

// ---------------- launch -----------------------------------------------------
extern "C" void kernel_launch(void* const* d_in, const int* in_sizes, int n_in,
                              void* d_out, int out_size) {
    const float* img    = (const float*)d_in[0];
    const float* txt    = (const float*)d_in[1];
    const float* ln_t_g = (const float*)d_in[2];
    const float* ln_t_b = (const float*)d_in[3];
    const float* ln_l_g = (const float*)d_in[4];
    const float* ln_l_b = (const float*)d_in[5];
    const float* W1     = (const float*)d_in[6];
    const float* b1     = (const float*)d_in[7];
    const float* W2     = (const float*)d_in[8];
    const float* b2     = (const float*)d_in[9];
    float* out = (float*)d_out;

    k_mean<<<dim3(NF, 5), 128>>>(img);
    k_ln<<<NF + 1, 256>>>(txt, ln_l_g, ln_l_b, ln_t_g, ln_t_b);
    k_transpose<<<dim3(EMB / 32, NF / 32), dim3(32, 8)>>>();
    k_tvec<<<HID / 64, 64>>>(W1);
    k_gemm<<<dim3(NCOL / BN, NF / BM), 128>>>(W1);
    k_gates<<<NF, 128>>>(b1, W2, b2);
    k_select<<<1, 512>>>(out, out_size);
}

// round 2
// speedup vs baseline: 1.4469x; 1.4469x over previous
#include <cuda_runtime.h>
#include <math.h>

#define NF   512          // frames
#define TOK  196          // tokens per frame
#define EMB  2560         // embed dim
#define HID  512          // hidden dim
#define E4   (EMB/4)      // 640 float4 per row
#define NCOL (HID + NF)   // 1024 columns of fused GEMM output

// ---------------- scratch (device globals; no allocation allowed) ----------
__device__ float    g_pooled[NF * EMB];     // pooled -> layernormed in place
__device__ float    g_pooledT[EMB * NF];    // transpose for GEMM B operand
__device__ float    g_txt[EMB];             // layernormed text
__device__ float    g_inv[NF];              // 1 / max(||pooled_ln row||, 1e-8)
__device__ float    g_tvec[HID];            // txt_ln @ W1_top
__device__ float    g_E[NF * NCOL];         // [pooled_ln@W1_bot | pooled_ln@pooled_ln^T]
__device__ float    g_gates[NF];
__device__ unsigned g_mask[NF * 16];        // f2f > 0.98 bitmask, 512 bits/row

// ---------------- helpers ---------------------------------------------------
template<int NW>
__device__ __forceinline__ float block_sum(float v, float* sh) {
    #pragma unroll
    for (int o = 16; o > 0; o >>= 1) v += __shfl_down_sync(0xffffffffu, v, o);
    if ((threadIdx.x & 31) == 0) sh[threadIdx.x >> 5] = v;
    __syncthreads();
    float tot = 0.f;
    #pragma unroll
    for (int i = 0; i < NW; i++) tot += sh[i];
    __syncthreads();   // allow sh reuse
    return tot;
}

// ---------------- 1) mean over tokens (HBM-bound, 1.03 GB read) -------------
__global__ void __launch_bounds__(128) k_mean(const float* __restrict__ img) {
    int f  = blockIdx.x;
    int e4 = blockIdx.y * 128 + threadIdx.x;                 // 0..639
    const float4* p = reinterpret_cast<const float4*>(img) + (size_t)f * TOK * E4 + e4;
    float4 a = make_float4(0.f, 0.f, 0.f, 0.f);
    #pragma unroll 4
    for (int t = 0; t < TOK; t++) {
        float4 v = p[(size_t)t * E4];
        a.x += v.x; a.y += v.y; a.z += v.z; a.w += v.w;
    }
    const float s = 1.0f / (float)TOK;
    a.x *= s; a.y *= s; a.z *= s; a.w *= s;
    reinterpret_cast<float4*>(g_pooled)[(size_t)f * E4 + e4] = a;
}

// ---------------- 2) layernorm (frames in-place; block NF handles text) -----
__global__ void __launch_bounds__(256) k_ln(const float* __restrict__ txt,
                                            const float* __restrict__ lng,
                                            const float* __restrict__ lnb,
                                            const float* __restrict__ tg,
                                            const float* __restrict__ tb) {
    __shared__ float sh[8];
    int  bid   = blockIdx.x;
    bool istxt = (bid == NF);
    const float* x   = istxt ? txt : (g_pooled + (size_t)bid * EMB);
    const float* gam = istxt ? tg  : lng;
    const float* bet = istxt ? tb  : lnb;

    if (istxt) {
        // zero tvec accumulator (k_tvec runs later in-stream)
        g_tvec[threadIdx.x] = 0.f;
        g_tvec[threadIdx.x + 256] = 0.f;
    }

    float v[10]; float s = 0.f, s2 = 0.f;
    #pragma unroll
    for (int i = 0; i < 10; i++) {
        v[i] = x[threadIdx.x + i * 256];
        s += v[i]; s2 += v[i] * v[i];
    }
    float S  = block_sum<8>(s,  sh);
    float S2 = block_sum<8>(s2, sh);
    float mean = S * (1.0f / EMB);
    float var  = S2 * (1.0f / EMB) - mean * mean;
    float rstd = rsqrtf(var + 1e-5f);

    float n2 = 0.f;
    float* dst = istxt ? g_txt : (g_pooled + (size_t)bid * EMB);
    #pragma unroll
    for (int i = 0; i < 10; i++) {
        int e = threadIdx.x + i * 256;
        float y = (v[i] - mean) * rstd * gam[e] + bet[e];
        dst[e] = y;
        n2 += y * y;
    }
    if (!istxt) {
        float N2 = block_sum<8>(n2, sh);
        if (threadIdx.x == 0) g_inv[bid] = 1.0f / fmaxf(sqrtf(N2), 1e-8f);
    }
}

// ---------------- 3a) transpose pooled_ln -> [EMB, NF] ----------------------
__global__ void __launch_bounds__(256) k_transpose() {
    __shared__ float tile[32][33];
    int x  = blockIdx.x * 32 + threadIdx.x;   // embed col (0..2559)
    int y0 = blockIdx.y * 32;                 // frame row base
    #pragma unroll
    for (int j = threadIdx.y; j < 32; j += 8)
        tile[j][threadIdx.x] = g_pooled[(size_t)(y0 + j) * EMB + x];
    __syncthreads();
    int fo = y0 + threadIdx.x;                // output col (frame)
    int e0 = blockIdx.x * 32;                 // output row base (embed)
    #pragma unroll
    for (int j = threadIdx.y; j < 32; j += 8)
        g_pooledT[(size_t)(e0 + j) * NF + fo] = tile[threadIdx.x][j];
}

// ---------------- 3b) tvec = txt_ln @ W1_top  [HID]  (k-split + atomics) ----
// grid.x = EMB/128 = 20 blocks, 512 threads; thread tid owns column h=tid.
// Fully coalesced: consecutive threads read consecutive W1 columns.
__global__ void __launch_bounds__(512) k_tvec(const float* __restrict__ W1) {
    int h  = threadIdx.x;                 // 0..511
    int e0 = blockIdx.x * 128;
    __shared__ float st[128];
    if (threadIdx.x < 128) st[threadIdx.x] = g_txt[e0 + threadIdx.x];
    __syncthreads();
    float s = 0.f;
    const float* w = W1 + (size_t)e0 * HID + h;
    #pragma unroll 8
    for (int e = 0; e < 128; e++) s = fmaf(st[e], w[(size_t)e * HID], s);
    atomicAdd(&g_tvec[h], s);
}

// ---------------- 4) fused GEMM  E = A @ [W1_bot | A^T]  (fp32 SIMT) --------
// A = g_pooled [512, 2560] row-major. Both B halves have row stride 512.
#define BM 64
#define BN 64
#define BK 16
__global__ void __launch_bounds__(128) k_gemm(const float* __restrict__ W1) {
    __shared__ float As[BK][BM + 4];   // [k][m], row stride 68 floats (16B aligned)
    __shared__ float Bs[BK][BN];       // [k][n]

    int bn = blockIdx.x * BN;          // 0..960
    int bm = blockIdx.y * BM;          // 0..448
    const float* Bbase = (bn < HID) ? (W1 + (size_t)EMB * HID + bn)
                                    : (g_pooledT + (bn - HID));
    const float* Abase = g_pooled + (size_t)bm * EMB;

    int tid = threadIdx.x;
    int tx  = tid & 15;                // 4 output cols each
    int ty  = tid >> 4;                // 8 output rows each

    float acc[8][4];
    #pragma unroll
    for (int i = 0; i < 8; i++)
        #pragma unroll
        for (int j = 0; j < 4; j++) acc[i][j] = 0.f;

    for (int k0 = 0; k0 < EMB; k0 += BK) {
        // A tile: 64 rows x 16 k, float4 along k, stored transposed
        {
            int c4 = tid & 3;          // k/4
            int r  = tid >> 2;         // 0..31
            #pragma unroll
            for (int i = 0; i < 2; i++) {
                int rr = r + i * 32;
                float4 va = *reinterpret_cast<const float4*>(
                    Abase + (size_t)rr * EMB + k0 + c4 * 4);
                As[c4 * 4 + 0][rr] = va.x;
                As[c4 * 4 + 1][rr] = va.y;
                As[c4 * 4 + 2][rr] = va.z;
                As[c4 * 4 + 3][rr] = va.w;
            }
        }
        // B tile: 16 k-rows x 64 n, float4 along n
        {
            int c4 = tid & 15;         // n/4
            int r  = tid >> 4;         // 0..7
            #pragma unroll
            for (int i = 0; i < 2; i++) {
                int kk = r + i * 8;
                float4 vb = *reinterpret_cast<const float4*>(
                    Bbase + (size_t)(k0 + kk) * 512 + c4 * 4);
                *reinterpret_cast<float4*>(&Bs[kk][c4 * 4]) = vb;
            }
        }
        __syncthreads();
        #pragma unroll
        for (int k = 0; k < BK; k++) {
            float4 a0 = *reinterpret_cast<const float4*>(&As[k][ty * 8]);
            float4 a1 = *reinterpret_cast<const float4*>(&As[k][ty * 8 + 4]);
            float4 b0 = *reinterpret_cast<const float4*>(&Bs[k][tx * 4]);
            float a[8] = {a0.x, a0.y, a0.z, a0.w, a1.x, a1.y, a1.z, a1.w};
            float b[4] = {b0.x, b0.y, b0.z, b0.w};
            #pragma unroll
            for (int i = 0; i < 8; i++)
                #pragma unroll
                for (int j = 0; j < 4; j++)
                    acc[i][j] = fmaf(a[i], b[j], acc[i][j]);
        }
        __syncthreads();
    }
    #pragma unroll
    for (int i = 0; i < 8; i++) {
        float4 o = make_float4(acc[i][0], acc[i][1], acc[i][2], acc[i][3]);
        *reinterpret_cast<float4*>(
            &g_E[(size_t)(bm + ty * 8 + i) * NCOL + bn + tx * 4]) = o;
    }
}

// ---------------- 5) gates + f2f bitmask -------------------------------------
__global__ void __launch_bounds__(128) k_gates(const float* __restrict__ b1,
                                               const float* __restrict__ W2,
                                               const float* __restrict__ b2) {
    __shared__ float sh[4];
    int f   = blockIdx.x;
    int tid = threadIdx.x;

    float s = 0.f;
    #pragma unroll
    for (int h = tid; h < HID; h += 128) {
        float v = g_E[(size_t)f * NCOL + h] + g_tvec[h] + b1[h];
        s += fmaxf(v, 0.f) * W2[h];
    }
    float tot = block_sum<4>(s, sh);
    if (tid == 0) g_gates[f] = 1.0f / (1.0f + expf(-(tot + b2[0])));

    float invi = g_inv[f];
    #pragma unroll
    for (int j = tid; j < NF; j += 128) {
        float c = g_E[(size_t)f * NCOL + HID + j] * invi * g_inv[j];
        unsigned bal = __ballot_sync(0xffffffffu, c > 0.98f);
        if ((j & 31) == 0) g_mask[f * 16 + (j >> 5)] = bal;
    }
}

// ---------------- 6) greedy selection (repeated argmax == sorted scan) ------
__global__ void __launch_bounds__(512) k_select(float* __restrict__ out, int out_size) {
    __shared__ float sg[NF];
    __shared__ int   svis[NF];
    __shared__ int   ssel[NF];
    __shared__ float rk[NF];
    __shared__ int   ri[NF];
    int tid = threadIdx.x;
    sg[tid]  = g_gates[tid];
    svis[tid] = 0;
    ssel[tid] = 0;
    __syncthreads();

    for (int it = 0; it < 32; it++) {
        rk[tid] = svis[tid] ? -1e30f : sg[tid];
        ri[tid] = tid;
        __syncthreads();
        #pragma unroll
        for (int off = 256; off > 0; off >>= 1) {
            if (tid < off) {
                float ko = rk[tid + off]; int io = ri[tid + off];
                // higher gate wins; tie -> lower index (matches stable argsort(-g))
                if (ko > rk[tid] || (ko == rk[tid] && io < ri[tid])) {
                    rk[tid] = ko; ri[tid] = io;
                }
            }
            __syncthreads();
        }
        int   cur  = ri[0];
        float best = rk[0];
        if (best < -1e29f) break;          // everyone visited
        if (tid == 0) ssel[cur] = 1;
        // visited |= (f2f[cur] > thrd); diagonal bit marks cur itself
        unsigned w = g_mask[cur * 16 + (tid >> 5)];
        if (w & (1u << (tid & 31))) svis[tid] = 1;
        __syncthreads();
    }

    if (tid < out_size)        out[tid]      = (float)ssel[tid];
    if (NF + tid < out_size)   out[NF + tid] = sg[tid];
}

// ---------------- launch -----------------------------------------------------
extern "C" void kernel_launch(void* const* d_in, const int* in_sizes, int n_in,
                              void* d_out, int out_size) {
    const float* img    = (const float*)d_in[0];
    const float* txt    = (const float*)d_in[1];
    const float* ln_t_g = (const float*)d_in[2];
    const float* ln_t_b = (const float*)d_in[3];
    const float* ln_l_g = (const float*)d_in[4];
    const float* ln_l_b = (const float*)d_in[5];
    const float* W1     = (const float*)d_in[6];
    const float* b1     = (const float*)d_in[7];
    const float* W2     = (const float*)d_in[8];
    const float* b2     = (const float*)d_in[9];
    float* out = (float*)d_out;

    k_mean<<<dim3(NF, 5), 128>>>(img);
    k_ln<<<NF + 1, 256>>>(txt, ln_l_g, ln_l_b, ln_t_g, ln_t_b);
    k_transpose<<<dim3(EMB / 32, NF / 32), dim3(32, 8)>>>();
    k_tvec<<<EMB / 128, 512>>>(W1);
    k_gemm<<<dim3(NCOL / BN, NF / BM), 128>>>(W1);
    k_gates<<<NF, 128>>>(b1, W2, b2);
    k_select<<<1, 512>>>(out, out_size);
}

// round 3
// speedup vs baseline: 1.9465x; 1.3453x over previous
#include <cuda_runtime.h>
#include <math.h>

#define NF   512          // frames
#define TOK  196          // tokens per frame
#define EMB  2560         // embed dim
#define HID  512          // hidden dim
#define E4   (EMB/4)      // 640 float4 per row
#define NCOL (HID + NF)   // 1024 columns of fused GEMM output
#define KSPLIT 4
#define KCHUNK (EMB / KSPLIT)   // 640

// ---------------- scratch (device globals; no allocation allowed) ----------
__device__ float    g_pooled[NF * EMB];     // pooled -> layernormed in place
__device__ float    g_pooledT[EMB * NF];    // transpose for GEMM B operand
__device__ float    g_txt[EMB];             // layernormed text
__device__ float    g_inv[NF];              // 1 / max(||pooled_ln row||, 1e-8)
__device__ float    g_tvec[HID];            // txt_ln @ W1_top
__device__ float    g_E[KSPLIT * NF * NCOL];// k-split partials of fused GEMM
__device__ float    g_gates[NF];
__device__ unsigned g_mask[NF * 16];        // f2f > 0.98 bitmask, 512 bits/row

// ---------------- helpers ---------------------------------------------------
template<int NW>
__device__ __forceinline__ float block_sum(float v, float* sh) {
    #pragma unroll
    for (int o = 16; o > 0; o >>= 1) v += __shfl_down_sync(0xffffffffu, v, o);
    if ((threadIdx.x & 31) == 0) sh[threadIdx.x >> 5] = v;
    __syncthreads();
    float tot = 0.f;
    #pragma unroll
    for (int i = 0; i < NW; i++) tot += sh[i];
    __syncthreads();   // allow sh reuse
    return tot;
}

// ---------------- 1) mean over tokens (HBM-bound, 1.03 GB read) -------------
__global__ void __launch_bounds__(128) k_mean(const float* __restrict__ img) {
    int f  = blockIdx.x;
    int e4 = blockIdx.y * 128 + threadIdx.x;                 // 0..639
    const float4* p = reinterpret_cast<const float4*>(img) + (size_t)f * TOK * E4 + e4;
    float4 a = make_float4(0.f, 0.f, 0.f, 0.f);
    #pragma unroll 4
    for (int t = 0; t < TOK; t++) {
        float4 v = p[(size_t)t * E4];
        a.x += v.x; a.y += v.y; a.z += v.z; a.w += v.w;
    }
    const float s = 1.0f / (float)TOK;
    a.x *= s; a.y *= s; a.z *= s; a.w *= s;
    reinterpret_cast<float4*>(g_pooled)[(size_t)f * E4 + e4] = a;
}

// ---------------- 2) layernorm (frames in-place; block NF handles text) -----
__global__ void __launch_bounds__(256) k_ln(const float* __restrict__ txt,
                                            const float* __restrict__ lng,
                                            const float* __restrict__ lnb,
                                            const float* __restrict__ tg,
                                            const float* __restrict__ tb) {
    __shared__ float sh[8];
    int  bid   = blockIdx.x;
    bool istxt = (bid == NF);
    const float* x   = istxt ? txt : (g_pooled + (size_t)bid * EMB);
    const float* gam = istxt ? tg  : lng;
    const float* bet = istxt ? tb  : lnb;

    if (istxt) {
        // zero tvec accumulator (k_tvec runs later in-stream)
        g_tvec[threadIdx.x] = 0.f;
        g_tvec[threadIdx.x + 256] = 0.f;
    }

    float v[10]; float s = 0.f, s2 = 0.f;
    #pragma unroll
    for (int i = 0; i < 10; i++) {
        v[i] = x[threadIdx.x + i * 256];
        s += v[i]; s2 += v[i] * v[i];
    }
    float S  = block_sum<8>(s,  sh);
    float S2 = block_sum<8>(s2, sh);
    float mean = S * (1.0f / EMB);
    float var  = S2 * (1.0f / EMB) - mean * mean;
    float rstd = rsqrtf(var + 1e-5f);

    float n2 = 0.f;
    float* dst = istxt ? g_txt : (g_pooled + (size_t)bid * EMB);
    #pragma unroll
    for (int i = 0; i < 10; i++) {
        int e = threadIdx.x + i * 256;
        float y = (v[i] - mean) * rstd * gam[e] + bet[e];
        dst[e] = y;
        n2 += y * y;
    }
    if (!istxt) {
        float N2 = block_sum<8>(n2, sh);
        if (threadIdx.x == 0) g_inv[bid] = 1.0f / fmaxf(sqrtf(N2), 1e-8f);
    }
}

// ---------------- 3a) transpose pooled_ln -> [EMB, NF] ----------------------
__global__ void __launch_bounds__(256) k_transpose() {
    __shared__ float tile[32][33];
    int x  = blockIdx.x * 32 + threadIdx.x;   // embed col (0..2559)
    int y0 = blockIdx.y * 32;                 // frame row base
    #pragma unroll
    for (int j = threadIdx.y; j < 32; j += 8)
        tile[j][threadIdx.x] = g_pooled[(size_t)(y0 + j) * EMB + x];
    __syncthreads();
    int fo = y0 + threadIdx.x;                // output col (frame)
    int e0 = blockIdx.x * 32;                 // output row base (embed)
    #pragma unroll
    for (int j = threadIdx.y; j < 32; j += 8)
        g_pooledT[(size_t)(e0 + j) * NF + fo] = tile[threadIdx.x][j];
}

// ---------------- 3b) tvec = txt_ln @ W1_top  (k-split 160 blocks) ----------
__global__ void __launch_bounds__(512) k_tvec(const float* __restrict__ W1) {
    int h  = threadIdx.x;                 // 0..511
    int e0 = blockIdx.x * 16;
    __shared__ float st[16];
    if (threadIdx.x < 16) st[threadIdx.x] = g_txt[e0 + threadIdx.x];
    __syncthreads();
    float s = 0.f;
    const float* w = W1 + (size_t)e0 * HID + h;
    #pragma unroll
    for (int e = 0; e < 16; e++) s = fmaf(st[e], w[(size_t)e * HID], s);
    atomicAdd(&g_tvec[h], s);
}

// ---------------- 4) fused GEMM  E = A @ [W1_bot | A^T]  (fp32, k-split) ----
// A = g_pooled [512, 2560] row-major. Both B halves have row stride 512.
#define BM 64
#define BN 64
#define BK 16
#define NSTEP (KCHUNK / BK)   // 40
__global__ void __launch_bounds__(128) k_gemm(const float* __restrict__ W1) {
    __shared__ float As[2][BK][BM + 4];
    __shared__ float Bs[2][BK][BN];

    int bn = blockIdx.x * BN;          // 0..960
    int bm = blockIdx.y * BM;          // 0..448
    int ks = blockIdx.z;               // k-split index
    int kbase = ks * KCHUNK;
    const float* Bbase = (bn < HID) ? (W1 + (size_t)EMB * HID + bn)
                                    : (g_pooledT + (bn - HID));
    const float* Abase = g_pooled + (size_t)bm * EMB + kbase;
    Bbase += (size_t)kbase * 512;

    int tid = threadIdx.x;
    int tx  = tid & 15;                // 4 output cols each
    int ty  = tid >> 4;                // 8 output rows each

    // loader indexing
    int ac4 = tid & 3;                 // A: k/4
    int ar  = tid >> 2;                // A: row 0..31 (+32)
    int bc4 = tid & 15;                // B: n/4
    int br  = tid >> 4;                // B: k-row 0..7 (+8)

    float acc[8][4];
    #pragma unroll
    for (int i = 0; i < 8; i++)
        #pragma unroll
        for (int j = 0; j < 4; j++) acc[i][j] = 0.f;

    float4 pa[2], pb[2];
    // prefetch step 0
    #pragma unroll
    for (int i = 0; i < 2; i++) {
        pa[i] = *reinterpret_cast<const float4*>(Abase + (size_t)(ar + i * 32) * EMB + ac4 * 4);
        pb[i] = *reinterpret_cast<const float4*>(Bbase + (size_t)(br + i * 8) * 512 + bc4 * 4);
    }
    // store step 0 into buffer 0
    #pragma unroll
    for (int i = 0; i < 2; i++) {
        int rr = ar + i * 32;
        As[0][ac4 * 4 + 0][rr] = pa[i].x;
        As[0][ac4 * 4 + 1][rr] = pa[i].y;
        As[0][ac4 * 4 + 2][rr] = pa[i].z;
        As[0][ac4 * 4 + 3][rr] = pa[i].w;
        *reinterpret_cast<float4*>(&Bs[0][br + i * 8][bc4 * 4]) = pb[i];
    }
    __syncthreads();

    for (int s = 0; s < NSTEP; s++) {
        int cur = s & 1;
        // prefetch next step's tiles into registers (overlaps compute)
        if (s + 1 < NSTEP) {
            const float* An = Abase + (s + 1) * BK;
            const float* Bn = Bbase + (size_t)(s + 1) * BK * 512;
            #pragma unroll
            for (int i = 0; i < 2; i++) {
                pa[i] = *reinterpret_cast<const float4*>(An + (size_t)(ar + i * 32) * EMB + ac4 * 4);
                pb[i] = *reinterpret_cast<const float4*>(Bn + (size_t)(br + i * 8) * 512 + bc4 * 4);
            }
        }
        // compute current buffer
        #pragma unroll
        for (int k = 0; k < BK; k++) {
            float4 a0 = *reinterpret_cast<const float4*>(&As[cur][k][ty * 8]);
            float4 a1 = *reinterpret_cast<const float4*>(&As[cur][k][ty * 8 + 4]);
            float4 b0 = *reinterpret_cast<const float4*>(&Bs[cur][k][tx * 4]);
            float a[8] = {a0.x, a0.y, a0.z, a0.w, a1.x, a1.y, a1.z, a1.w};
            float b[4] = {b0.x, b0.y, b0.z, b0.w};
            #pragma unroll
            for (int i = 0; i < 8; i++)
                #pragma unroll
                for (int j = 0; j < 4; j++)
                    acc[i][j] = fmaf(a[i], b[j], acc[i][j]);
        }
        // store prefetched tiles into alternate buffer
        if (s + 1 < NSTEP) {
            int nxt = cur ^ 1;
            #pragma unroll
            for (int i = 0; i < 2; i++) {
                int rr = ar + i * 32;
                As[nxt][ac4 * 4 + 0][rr] = pa[i].x;
                As[nxt][ac4 * 4 + 1][rr] = pa[i].y;
                As[nxt][ac4 * 4 + 2][rr] = pa[i].z;
                As[nxt][ac4 * 4 + 3][rr] = pa[i].w;
                *reinterpret_cast<float4*>(&Bs[nxt][br + i * 8][bc4 * 4]) = pb[i];
            }
            __syncthreads();
        }
    }

    float* Eout = g_E + (size_t)ks * NF * NCOL;
    #pragma unroll
    for (int i = 0; i < 8; i++) {
        float4 o = make_float4(acc[i][0], acc[i][1], acc[i][2], acc[i][3]);
        *reinterpret_cast<float4*>(
            &Eout[(size_t)(bm + ty * 8 + i) * NCOL + bn + tx * 4]) = o;
    }
}

// ---------------- 5) gates + f2f bitmask (sums k-split partials) -------------
__global__ void __launch_bounds__(128) k_gates(const float* __restrict__ b1,
                                               const float* __restrict__ W2,
                                               const float* __restrict__ b2) {
    __shared__ float sh[4];
    int f   = blockIdx.x;
    int tid = threadIdx.x;
    const size_t P = (size_t)NF * NCOL;

    float s = 0.f;
    #pragma unroll
    for (int h = tid; h < HID; h += 128) {
        size_t idx = (size_t)f * NCOL + h;
        float v = g_E[idx] + g_E[idx + P] + g_E[idx + 2 * P] + g_E[idx + 3 * P]
                + g_tvec[h] + b1[h];
        s += fmaxf(v, 0.f) * W2[h];
    }
    float tot = block_sum<4>(s, sh);
    if (tid == 0) g_gates[f] = 1.0f / (1.0f + expf(-(tot + b2[0])));

    float invi = g_inv[f];
    #pragma unroll
    for (int j = tid; j < NF; j += 128) {
        size_t idx = (size_t)f * NCOL + HID + j;
        float d = g_E[idx] + g_E[idx + P] + g_E[idx + 2 * P] + g_E[idx + 3 * P];
        float c = d * invi * g_inv[j];
        unsigned bal = __ballot_sync(0xffffffffu, c > 0.98f);
        if ((j & 31) == 0) g_mask[f * 16 + (j >> 5)] = bal;
    }
}

// ---------------- 6) greedy selection (repeated argmax == sorted scan) ------
__global__ void __launch_bounds__(512) k_select(float* __restrict__ out, int out_size) {
    __shared__ float sg[NF];
    __shared__ int   svis[NF];
    __shared__ int   ssel[NF];
    __shared__ float rk[NF];
    __shared__ int   ri[NF];
    int tid = threadIdx.x;
    sg[tid]  = g_gates[tid];
    svis[tid] = 0;
    ssel[tid] = 0;
    __syncthreads();

    for (int it = 0; it < 32; it++) {
        rk[tid] = svis[tid] ? -1e30f : sg[tid];
        ri[tid] = tid;
        __syncthreads();
        #pragma unroll
        for (int off = 256; off > 0; off >>= 1) {
            if (tid < off) {
                float ko = rk[tid + off]; int io = ri[tid + off];
                if (ko > rk[tid] || (ko == rk[tid] && io < ri[tid])) {
                    rk[tid] = ko; ri[tid] = io;
                }
            }
            __syncthreads();
        }
        int   cur  = ri[0];
        float best = rk[0];
        if (best < -1e29f) break;          // everyone visited
        if (tid == 0) ssel[cur] = 1;
        unsigned w = g_mask[cur * 16 + (tid >> 5)];
        if (w & (1u << (tid & 31))) svis[tid] = 1;
        __syncthreads();
    }

    if (tid < out_size)        out[tid]      = (float)ssel[tid];
    if (NF + tid < out_size)   out[NF + tid] = sg[tid];
}

// ---------------- launch -----------------------------------------------------
extern "C" void kernel_launch(void* const* d_in, const int* in_sizes, int n_in,
                              void* d_out, int out_size) {
    const float* img    = (const float*)d_in[0];
    const float* txt    = (const float*)d_in[1];
    const float* ln_t_g = (const float*)d_in[2];
    const float* ln_t_b = (const float*)d_in[3];
    const float* ln_l_g = (const float*)d_in[4];
    const float* ln_l_b = (const float*)d_in[5];
    const float* W1     = (const float*)d_in[6];
    const float* b1     = (const float*)d_in[7];
    const float* W2     = (const float*)d_in[8];
    const float* b2     = (const float*)d_in[9];
    float* out = (float*)d_out;

    k_mean<<<dim3(NF, 5), 128>>>(img);
    k_ln<<<NF + 1, 256>>>(txt, ln_l_g, ln_l_b, ln_t_g, ln_t_b);
    k_transpose<<<dim3(EMB / 32, NF / 32), dim3(32, 8)>>>();
    k_tvec<<<EMB / 16, 512>>>(W1);
    k_gemm<<<dim3(NCOL / BN, NF / BM, KSPLIT), 128>>>(W1);
    k_gates<<<NF, 128>>>(b1, W2, b2);
    k_select<<<1, 512>>>(out, out_size);
}

// round 5
// speedup vs baseline: 2.1699x; 1.1147x over previous
#include <cuda_runtime.h>
#include <cuda_bf16.h>
#include <math.h>
#include <stdint.h>

#define NF   512
#define TOK  196
#define EMB  2560
#define HID  512
#define E4   (EMB/4)
#define NCOL (HID + NF)          // 1024
#define KSPLIT 4
#define KCHUNK (EMB / KSPLIT)    // 640
#define BK 32
#define NSTAGE (KCHUNK / BK)     // 20
#define ASTR 40                  // smem row stride in bf16 (32 + 8 pad)

// ---------------- scratch (device globals) ----------------------------------
__device__ float         g_pooled[NF * EMB];
__device__ __nv_bfloat16 g_Ahi[NF * EMB];      // layernormed pooled, bf16 hi
__device__ __nv_bfloat16 g_Alo[NF * EMB];      // residual lo
__device__ __nv_bfloat16 g_Whi[HID * EMB];     // W1_bot^T bf16 hi  [n][k]
__device__ __nv_bfloat16 g_Wlo[HID * EMB];     // W1_bot^T residual lo
__device__ float         g_txt[EMB];
__device__ float         g_inv[NF];
__device__ float         g_tvec[HID];
__device__ float         g_E[KSPLIT * NF * NCOL];
__device__ float         g_gates[NF];
__device__ unsigned      g_mask[NF * 16];

// ---------------- PTX helpers -------------------------------------------------
__device__ __forceinline__ uint32_t smem_u32(const void* p) {
    uint32_t a;
    asm("{ .reg .u64 t; cvta.to.shared.u64 t, %1; cvt.u32.u64 %0, t; }" : "=r"(a) : "l"(p));
    return a;
}
__device__ __forceinline__ void cpa16(uint32_t d, const void* s) {
    asm volatile("cp.async.cg.shared.global [%0], [%1], 16;" :: "r"(d), "l"(s));
}
#define CP_COMMIT() asm volatile("cp.async.commit_group;" ::: "memory")
template<int N>
__device__ __forceinline__ void cp_wait() {
    asm volatile("cp.async.wait_group %0;" :: "n"(N) : "memory");
}
__device__ __forceinline__ void mma16816(float* d, const uint32_t* a, const uint32_t* b) {
    asm volatile(
        "mma.sync.aligned.m16n8k16.row.col.f32.bf16.bf16.f32 "
        "{%0,%1,%2,%3}, {%4,%5,%6,%7}, {%8,%9}, {%0,%1,%2,%3};"
        : "+f"(d[0]), "+f"(d[1]), "+f"(d[2]), "+f"(d[3])
        : "r"(a[0]), "r"(a[1]), "r"(a[2]), "r"(a[3]), "r"(b[0]), "r"(b[1]));
}

// ---------------- helpers ------------------------------------------------------
template<int NW>
__device__ __forceinline__ float block_sum(float v, float* sh) {
    #pragma unroll
    for (int o = 16; o > 0; o >>= 1) v += __shfl_down_sync(0xffffffffu, v, o);
    if ((threadIdx.x & 31) == 0) sh[threadIdx.x >> 5] = v;
    __syncthreads();
    float tot = 0.f;
    #pragma unroll
    for (int i = 0; i < NW; i++) tot += sh[i];
    __syncthreads();
    return tot;
}

// ---------------- 1) mean over tokens ------------------------------------------
__global__ void __launch_bounds__(128) k_mean(const float* __restrict__ img) {
    int f  = blockIdx.x;
    int e4 = blockIdx.y * 128 + threadIdx.x;
    const float4* p = reinterpret_cast<const float4*>(img) + (size_t)f * TOK * E4 + e4;
    float4 a = make_float4(0.f, 0.f, 0.f, 0.f);
    #pragma unroll 4
    for (int t = 0; t < TOK; t++) {
        float4 v = p[(size_t)t * E4];
        a.x += v.x; a.y += v.y; a.z += v.z; a.w += v.w;
    }
    const float s = 1.0f / (float)TOK;
    a.x *= s; a.y *= s; a.z *= s; a.w *= s;
    reinterpret_cast<float4*>(g_pooled)[(size_t)f * E4 + e4] = a;
}

// ---------------- 2) layernorm -> bf16 hi/lo + norms ----------------------------
__global__ void __launch_bounds__(256) k_ln(const float* __restrict__ txt,
                                            const float* __restrict__ lng,
                                            const float* __restrict__ lnb,
                                            const float* __restrict__ tg,
                                            const float* __restrict__ tb) {
    __shared__ float sh[8];
    int  bid   = blockIdx.x;
    bool istxt = (bid == NF);
    const float* x   = istxt ? txt : (g_pooled + (size_t)bid * EMB);
    const float* gam = istxt ? tg  : lng;
    const float* bet = istxt ? tb  : lnb;

    if (istxt) {
        g_tvec[threadIdx.x] = 0.f;
        g_tvec[threadIdx.x + 256] = 0.f;
    }

    float v[10]; float s = 0.f, s2 = 0.f;
    #pragma unroll
    for (int i = 0; i < 10; i++) {
        v[i] = x[threadIdx.x + i * 256];
        s += v[i]; s2 += v[i] * v[i];
    }
    float S  = block_sum<8>(s,  sh);
    float S2 = block_sum<8>(s2, sh);
    float mean = S * (1.0f / EMB);
    float var  = S2 * (1.0f / EMB) - mean * mean;
    float rstd = rsqrtf(var + 1e-5f);

    float n2 = 0.f;
    #pragma unroll
    for (int i = 0; i < 10; i++) {
        int e = threadIdx.x + i * 256;
        float y = (v[i] - mean) * rstd * gam[e] + bet[e];
        if (istxt) {
            g_txt[e] = y;
        } else {
            __nv_bfloat16 hi = __float2bfloat16(y);
            g_Ahi[(size_t)bid * EMB + e] = hi;
            g_Alo[(size_t)bid * EMB + e] = __float2bfloat16(y - __bfloat162float(hi));
            n2 += y * y;
        }
    }
    if (!istxt) {
        float N2 = block_sum<8>(n2, sh);
        if (threadIdx.x == 0) g_inv[bid] = 1.0f / fmaxf(sqrtf(N2), 1e-8f);
    }
}

// ---------------- 3) W1_bot -> transposed bf16 hi/lo [n][k] ---------------------
__global__ void __launch_bounds__(256) k_wconv(const float* __restrict__ W1) {
    __shared__ float t[32][33];
    const float* Wb = W1 + (size_t)EMB * HID;
    int k0 = blockIdx.x * 32, n0 = blockIdx.y * 32;
    int tx = threadIdx.x, ty = threadIdx.y;
    #pragma unroll
    for (int j = ty; j < 32; j += 8)
        t[j][tx] = Wb[(size_t)(k0 + j) * HID + n0 + tx];
    __syncthreads();
    #pragma unroll
    for (int j = ty; j < 32; j += 8) {
        float x = t[tx][j];
        __nv_bfloat16 hi = __float2bfloat16(x);
        g_Whi[(size_t)(n0 + j) * EMB + k0 + tx] = hi;
        g_Wlo[(size_t)(n0 + j) * EMB + k0 + tx] = __float2bfloat16(x - __bfloat162float(hi));
    }
}

// ---------------- 3b) tvec = txt_ln @ W1_top ------------------------------------
__global__ void __launch_bounds__(512) k_tvec(const float* __restrict__ W1) {
    int h  = threadIdx.x;
    int e0 = blockIdx.x * 16;
    __shared__ float st[16];
    if (threadIdx.x < 16) st[threadIdx.x] = g_txt[e0 + threadIdx.x];
    __syncthreads();
    float s = 0.f;
    const float* w = W1 + (size_t)e0 * HID + h;
    #pragma unroll
    for (int e = 0; e < 16; e++) s = fmaf(st[e], w[(size_t)e * HID], s);
    atomicAdd(&g_tvec[h], s);
}

// ---------------- 4) HMMA GEMM  E = A @ [W1_bot | A^T]  -------------------------
// smem byte offsets within dynamic smem (ASTR=40 bf16 per row)
#define OFF_AHI(b) ((b) * 10240)
#define OFF_ALO(b) (20480 + (b) * 10240)
#define OFF_BHI(b) (40960 + (b) * 5120)
#define OFF_BLO(b) (51200 + (b) * 5120)
#define SM_TOT 61440

// async-load a tile of `rows` x BK bf16 (gmem row stride EMB) into smem
__device__ __forceinline__ void ld_tile(uint32_t sm, const __nv_bfloat16* g,
                                        int rows, int tid) {
    int nvec = rows * 4;                        // 16B vectors (BK*2/16 = 4 per row)
    for (int i = tid; i < nvec; i += 256) {
        int row = i >> 2, seg = i & 3;
        cpa16(sm + (uint32_t)(row * ASTR + seg * 8) * 2,
              g + (size_t)row * EMB + seg * 8);
    }
}

__global__ void __launch_bounds__(256, 2) k_gemm_mma() {
    extern __shared__ char smem[];
    uint32_t sbase = smem_u32(smem);
    int tid = threadIdx.x, wid = tid >> 5, lid = tid & 31;
    int bn = blockIdx.x * 64, bm = blockIdx.y * 128, ks = blockIdx.z;
    int kb = ks * KCHUNK;
    bool w1tile = (bn < HID);

    const __nv_bfloat16* Ah = g_Ahi + (size_t)bm * EMB + kb;
    const __nv_bfloat16* Al = g_Alo + (size_t)bm * EMB + kb;
    const __nv_bfloat16* Bh = w1tile ? (g_Whi + (size_t)bn * EMB + kb)
                                     : (g_Ahi + (size_t)(bn - HID) * EMB + kb);
    const __nv_bfloat16* Bl = g_Wlo + (size_t)bn * EMB + kb;   // W1 tiles only

    int wm = wid & 3;            // 4 warp rows * 32 = 128
    int wn = wid >> 2;           // 2 warp cols * 32 = 64
    int g  = lid >> 2;           // 0..7
    int t  = lid & 3;            // 0..3

    float acc[2][4][4];
    #pragma unroll
    for (int i = 0; i < 2; i++)
        #pragma unroll
        for (int j = 0; j < 4; j++)
            #pragma unroll
            for (int r = 0; r < 4; r++) acc[i][j][r] = 0.f;

    int np = w1tile ? 3 : 1;

    // prologue: load stage 0
    ld_tile(sbase + OFF_AHI(0), Ah, 128, tid);
    ld_tile(sbase + OFF_BHI(0), Bh, 64, tid);
    if (w1tile) {
        ld_tile(sbase + OFF_ALO(0), Al, 128, tid);
        ld_tile(sbase + OFF_BLO(0), Bl, 64, tid);
    }
    CP_COMMIT();

    for (int s = 0; s < NSTAGE; s++) {
        int buf = s & 1;
        if (s + 1 < NSTAGE) {
            int nb = buf ^ 1;
            ld_tile(sbase + OFF_AHI(nb), Ah + (s + 1) * BK, 128, tid);
            ld_tile(sbase + OFF_BHI(nb), Bh + (s + 1) * BK, 64, tid);
            if (w1tile) {
                ld_tile(sbase + OFF_ALO(nb), Al + (s + 1) * BK, 128, tid);
                ld_tile(sbase + OFF_BLO(nb), Bl + (s + 1) * BK, 64, tid);
            }
            CP_COMMIT();
            cp_wait<1>();
        } else {
            cp_wait<0>();
        }
        __syncthreads();

        for (int p = 0; p < np; p++) {
            const char* Asm = smem + ((p == 2) ? OFF_ALO(buf) : OFF_AHI(buf));
            const char* Bsm = smem + ((p == 1) ? OFF_BLO(buf) : OFF_BHI(buf));
            #pragma unroll
            for (int kk = 0; kk < BK; kk += 16) {
                uint32_t af[2][4], bf[4][2];
                #pragma unroll
                for (int mi = 0; mi < 2; mi++) {
                    int rm = wm * 32 + mi * 16;
                    af[mi][0] = *(const uint32_t*)(Asm + ((size_t)(rm + g)     * ASTR + kk + 2 * t) * 2);
                    af[mi][1] = *(const uint32_t*)(Asm + ((size_t)(rm + g + 8) * ASTR + kk + 2 * t) * 2);
                    af[mi][2] = *(const uint32_t*)(Asm + ((size_t)(rm + g)     * ASTR + kk + 2 * t + 8) * 2);
                    af[mi][3] = *(const uint32_t*)(Asm + ((size_t)(rm + g + 8) * ASTR + kk + 2 * t + 8) * 2);
                }
                #pragma unroll
                for (int ni = 0; ni < 4; ni++) {
                    int cn = wn * 32 + ni * 8;
                    bf[ni][0] = *(const uint32_t*)(Bsm + ((size_t)(cn + g) * ASTR + kk + 2 * t) * 2);
                    bf[ni][1] = *(const uint32_t*)(Bsm + ((size_t)(cn + g) * ASTR + kk + 2 * t + 8) * 2);
                }
                #pragma unroll
                for (int mi = 0; mi < 2; mi++)
                    #pragma unroll
                    for (int ni = 0; ni < 4; ni++)
                        mma16816(acc[mi][ni], af[mi], bf[ni]);
            }
        }
        __syncthreads();
    }

    // epilogue: write fragments to g_E partial buffer
    float* Eout = g_E + (size_t)ks * NF * NCOL;
    #pragma unroll
    for (int mi = 0; mi < 2; mi++) {
        #pragma unroll
        for (int ni = 0; ni < 4; ni++) {
            int r0 = bm + wm * 32 + mi * 16 + g;
            int c  = bn + wn * 32 + ni * 8 + 2 * t;
            *(float2*)&Eout[(size_t)r0 * NCOL + c]       = make_float2(acc[mi][ni][0], acc[mi][ni][1]);
            *(float2*)&Eout[(size_t)(r0 + 8) * NCOL + c] = make_float2(acc[mi][ni][2], acc[mi][ni][3]);
        }
    }
}

// ---------------- 5) gates + f2f bitmask -----------------------------------------
__global__ void __launch_bounds__(128) k_gates(const float* __restrict__ b1,
                                               const float* __restrict__ W2,
                                               const float* __restrict__ b2) {
    __shared__ float sh[4];
    int f   = blockIdx.x;
    int tid = threadIdx.x;
    const size_t P = (size_t)NF * NCOL;

    float s = 0.f;
    #pragma unroll
    for (int h = tid; h < HID; h += 128) {
        size_t idx = (size_t)f * NCOL + h;
        float v = g_E[idx] + g_E[idx + P] + g_E[idx + 2 * P] + g_E[idx + 3 * P]
                + g_tvec[h] + b1[h];
        s += fmaxf(v, 0.f) * W2[h];
    }
    float tot = block_sum<4>(s, sh);
    if (tid == 0) g_gates[f] = 1.0f / (1.0f + expf(-(tot + b2[0])));

    float invi = g_inv[f];
    #pragma unroll
    for (int j = tid; j < NF; j += 128) {
        size_t idx = (size_t)f * NCOL + HID + j;
        float d = g_E[idx] + g_E[idx + P] + g_E[idx + 2 * P] + g_E[idx + 3 * P];
        float c = d * invi * g_inv[j];
        unsigned bal = __ballot_sync(0xffffffffu, c > 0.98f);
        if ((j & 31) == 0) g_mask[f * 16 + (j >> 5)] = bal;
    }
}

// ---------------- 6) greedy selection --------------------------------------------
__global__ void __launch_bounds__(512) k_select(float* __restrict__ out, int out_size) {
    __shared__ float sg[NF];
    __shared__ int   svis[NF];
    __shared__ int   ssel[NF];
    __shared__ float rk[NF];
    __shared__ int   ri[NF];
    int tid = threadIdx.x;
    sg[tid]   = g_gates[tid];
    svis[tid] = 0;
    ssel[tid] = 0;
    __syncthreads();

    for (int it = 0; it < 32; it++) {
        rk[tid] = svis[tid] ? -1e30f : sg[tid];
        ri[tid] = tid;
        __syncthreads();
        #pragma unroll
        for (int off = 256; off > 0; off >>= 1) {
            if (tid < off) {
                float ko = rk[tid + off]; int io = ri[tid + off];
                if (ko > rk[tid] || (ko == rk[tid] && io < ri[tid])) {
                    rk[tid] = ko; ri[tid] = io;
                }
            }
            __syncthreads();
        }
        int   cur  = ri[0];
        float best = rk[0];
        if (best < -1e29f) break;
        if (tid == 0) ssel[cur] = 1;
        unsigned w = g_mask[cur * 16 + (tid >> 5)];
        if (w & (1u << (tid & 31))) svis[tid] = 1;
        __syncthreads();
    }

    if (tid < out_size)      out[tid]      = (float)ssel[tid];
    if (NF + tid < out_size) out[NF + tid] = sg[tid];
}

// ---------------- launch -----------------------------------------------------------
extern "C" void kernel_launch(void* const* d_in, const int* in_sizes, int n_in,
                              void* d_out, int out_size) {
    const float* img    = (const float*)d_in[0];
    const float* txt    = (const float*)d_in[1];
    const float* ln_t_g = (const float*)d_in[2];
    const float* ln_t_b = (const float*)d_in[3];
    const float* ln_l_g = (const float*)d_in[4];
    const float* ln_l_b = (const float*)d_in[5];
    const float* W1     = (const float*)d_in[6];
    const float* b1     = (const float*)d_in[7];
    const float* W2     = (const float*)d_in[8];
    const float* b2     = (const float*)d_in[9];
    float* out = (float*)d_out;

    cudaFuncSetAttribute(k_gemm_mma, cudaFuncAttributeMaxDynamicSharedMemorySize, SM_TOT);

    k_mean<<<dim3(NF, 5), 128>>>(img);
    k_ln<<<NF + 1, 256>>>(txt, ln_l_g, ln_l_b, ln_t_g, ln_t_b);
    k_wconv<<<dim3(EMB / 32, HID / 32), dim3(32, 8)>>>(W1);
    k_tvec<<<EMB / 16, 512>>>(W1);
    k_gemm_mma<<<dim3(NCOL / 64, NF / 128, KSPLIT), 256, SM_TOT>>>();
    k_gates<<<NF, 128>>>(b1, W2, b2);
    k_select<<<1, 512>>>(out, out_size);
}

// round 6
// speedup vs baseline: 2.3309x; 1.0742x over previous
#include <cuda_runtime.h>
#include <cuda_bf16.h>
#include <math.h>
#include <stdint.h>

#define NF   512
#define TOK  196
#define EMB  2560
#define HID  512
#define NCOL (HID + NF)          // 1024
#define KSPLIT 4
#define KCHUNK (EMB / KSPLIT)    // 640
#define BK 32
#define NSTAGE (KCHUNK / BK)     // 20
#define ASTR 40                  // smem row stride in bf16 (32 + 8 pad)

// ---------------- scratch (device globals) ----------------------------------
__device__ __nv_bfloat16 g_Ahi[NF * EMB];      // layernormed pooled, bf16 hi
__device__ __nv_bfloat16 g_Alo[NF * EMB];      // residual lo
__device__ __nv_bfloat16 g_Whi[HID * EMB];     // W1_bot^T bf16 hi  [n][k]
__device__ __nv_bfloat16 g_Wlo[HID * EMB];     // W1_bot^T residual lo
__device__ float         g_txt[EMB];
__device__ float         g_inv[NF];
__device__ float         g_tvec[HID];
__device__ float         g_E[KSPLIT * NF * NCOL];
__device__ float         g_gates[NF];
__device__ unsigned      g_mask[NF * 16];

// ---------------- PTX helpers -------------------------------------------------
__device__ __forceinline__ uint32_t smem_u32(const void* p) {
    uint32_t a;
    asm("{ .reg .u64 t; cvta.to.shared.u64 t, %1; cvt.u32.u64 %0, t; }" : "=r"(a) : "l"(p));
    return a;
}
__device__ __forceinline__ void cpa16(uint32_t d, const void* s) {
    asm volatile("cp.async.cg.shared.global [%0], [%1], 16;" :: "r"(d), "l"(s));
}
#define CP_COMMIT() asm volatile("cp.async.commit_group;" ::: "memory")
template<int N>
__device__ __forceinline__ void cp_wait() {
    asm volatile("cp.async.wait_group %0;" :: "n"(N) : "memory");
}
__device__ __forceinline__ void mma16816(float* d, const uint32_t* a, const uint32_t* b) {
    asm volatile(
        "mma.sync.aligned.m16n8k16.row.col.f32.bf16.bf16.f32 "
        "{%0,%1,%2,%3}, {%4,%5,%6,%7}, {%8,%9}, {%0,%1,%2,%3};"
        : "+f"(d[0]), "+f"(d[1]), "+f"(d[2]), "+f"(d[3])
        : "r"(a[0]), "r"(a[1]), "r"(a[2]), "r"(a[3]), "r"(b[0]), "r"(b[1]));
}
__device__ __forceinline__ void ldsm_x4(uint32_t* r, uint32_t addr) {
    asm volatile("ldmatrix.sync.aligned.m8n8.x4.shared.b16 {%0,%1,%2,%3}, [%4];"
        : "=r"(r[0]), "=r"(r[1]), "=r"(r[2]), "=r"(r[3]) : "r"(addr));
}

// ---------------- helpers ------------------------------------------------------
template<int NW>
__device__ __forceinline__ float block_sum(float v, float* sh) {
    #pragma unroll
    for (int o = 16; o > 0; o >>= 1) v += __shfl_down_sync(0xffffffffu, v, o);
    if ((threadIdx.x & 31) == 0) sh[threadIdx.x >> 5] = v;
    __syncthreads();
    float tot = 0.f;
    #pragma unroll
    for (int i = 0; i < NW; i++) tot += sh[i];
    __syncthreads();
    return tot;
}

// ---------------- 1) fused token-mean + layernorm -------------------------------
// blocks 0..NF-1: frame rows; block NF: text row (also zeroes g_tvec)
__global__ void __launch_bounds__(512) k_meanln(const float* __restrict__ img,
                                                const float* __restrict__ txt,
                                                const float* __restrict__ lng,
                                                const float* __restrict__ lnb,
                                                const float* __restrict__ tg,
                                                const float* __restrict__ tb) {
    __shared__ float sh[16];
    int  f     = blockIdx.x;
    bool istxt = (f == NF);
    int  tid   = threadIdx.x;

    float v[5];
    if (istxt) {
        g_tvec[tid] = 0.f;
        #pragma unroll
        for (int i = 0; i < 5; i++) v[i] = txt[tid + i * 512];
    } else {
        float a[5] = {0.f, 0.f, 0.f, 0.f, 0.f};
        const float* p = img + (size_t)f * TOK * EMB + tid;
        #pragma unroll 2
        for (int t = 0; t < TOK; t++) {
            #pragma unroll
            for (int i = 0; i < 5; i++) a[i] += p[(size_t)t * EMB + i * 512];
        }
        #pragma unroll
        for (int i = 0; i < 5; i++) v[i] = a[i] * (1.0f / TOK);
    }

    const float* gam = istxt ? tg : lng;
    const float* bet = istxt ? tb : lnb;
    float s = 0.f, s2 = 0.f;
    #pragma unroll
    for (int i = 0; i < 5; i++) { s += v[i]; s2 += v[i] * v[i]; }
    float S  = block_sum<16>(s,  sh);
    float S2 = block_sum<16>(s2, sh);
    float mean = S * (1.0f / EMB);
    float var  = S2 * (1.0f / EMB) - mean * mean;
    float rstd = rsqrtf(var + 1e-5f);

    float n2 = 0.f;
    #pragma unroll
    for (int i = 0; i < 5; i++) {
        int e = tid + i * 512;
        float y = (v[i] - mean) * rstd * gam[e] + bet[e];
        if (istxt) {
            g_txt[e] = y;
        } else {
            __nv_bfloat16 hi = __float2bfloat16(y);
            g_Ahi[(size_t)f * EMB + e] = hi;
            g_Alo[(size_t)f * EMB + e] = __float2bfloat16(y - __bfloat162float(hi));
            n2 += y * y;
        }
    }
    if (!istxt) {
        float N2 = block_sum<16>(n2, sh);
        if (tid == 0) g_inv[f] = 1.0f / fmaxf(sqrtf(N2), 1e-8f);
    }
}

// ---------------- 2) W1_bot -> transposed bf16 hi/lo [n][k] ---------------------
__global__ void __launch_bounds__(256) k_wconv(const float* __restrict__ W1) {
    __shared__ float t[32][33];
    const float* Wb = W1 + (size_t)EMB * HID;
    int k0 = blockIdx.x * 32, n0 = blockIdx.y * 32;
    int tx = threadIdx.x, ty = threadIdx.y;
    #pragma unroll
    for (int j = ty; j < 32; j += 8)
        t[j][tx] = Wb[(size_t)(k0 + j) * HID + n0 + tx];
    __syncthreads();
    #pragma unroll
    for (int j = ty; j < 32; j += 8) {
        float x = t[tx][j];
        __nv_bfloat16 hi = __float2bfloat16(x);
        g_Whi[(size_t)(n0 + j) * EMB + k0 + tx] = hi;
        g_Wlo[(size_t)(n0 + j) * EMB + k0 + tx] = __float2bfloat16(x - __bfloat162float(hi));
    }
}

// ---------------- 2b) tvec = txt_ln @ W1_top ------------------------------------
__global__ void __launch_bounds__(512) k_tvec(const float* __restrict__ W1) {
    int h  = threadIdx.x;
    int e0 = blockIdx.x * 16;
    __shared__ float st[16];
    if (threadIdx.x < 16) st[threadIdx.x] = g_txt[e0 + threadIdx.x];
    __syncthreads();
    float s = 0.f;
    const float* w = W1 + (size_t)e0 * HID + h;
    #pragma unroll
    for (int e = 0; e < 16; e++) s = fmaf(st[e], w[(size_t)e * HID], s);
    atomicAdd(&g_tvec[h], s);
}

// ---------------- 3) HMMA GEMM  E = A @ [W1_bot | A^T]  -------------------------
#define OFF_AHI(b) ((b) * 10240)
#define OFF_ALO(b) (20480 + (b) * 10240)
#define OFF_BHI(b) (40960 + (b) * 5120)
#define OFF_BLO(b) (51200 + (b) * 5120)
#define SM_TOT 61440

__device__ __forceinline__ void ld_tile(uint32_t sm, const __nv_bfloat16* g,
                                        int rows, int tid) {
    int nvec = rows * 4;
    for (int i = tid; i < nvec; i += 256) {
        int row = i >> 2, seg = i & 3;
        cpa16(sm + (uint32_t)(row * ASTR + seg * 8) * 2,
              g + (size_t)row * EMB + seg * 8);
    }
}

__global__ void __launch_bounds__(256, 2) k_gemm_mma() {
    extern __shared__ char smem[];
    uint32_t sbase = smem_u32(smem);
    int tid = threadIdx.x, wid = tid >> 5, lid = tid & 31;
    int bn = blockIdx.x * 64, bm = blockIdx.y * 128, ks = blockIdx.z;
    int kb = ks * KCHUNK;
    bool w1tile = (bn < HID);

    const __nv_bfloat16* Ah = g_Ahi + (size_t)bm * EMB + kb;
    const __nv_bfloat16* Al = g_Alo + (size_t)bm * EMB + kb;
    const __nv_bfloat16* Bh = w1tile ? (g_Whi + (size_t)bn * EMB + kb)
                                     : (g_Ahi + (size_t)(bn - HID) * EMB + kb);
    const __nv_bfloat16* Bl = g_Wlo + (size_t)bn * EMB + kb;   // W1 tiles only

    int wm = wid & 3;            // 4 warp rows * 32 = 128
    int wn = wid >> 2;           // 2 warp cols * 32 = 64
    int g  = lid >> 2;           // 0..7
    int t  = lid & 3;            // 0..3

    // ldmatrix per-lane address offsets (bytes, within a tile)
    uint32_t aoff = (uint32_t)((wm * 32 + (lid & 15)) * ASTR + (lid >> 4) * 8) * 2;
    uint32_t boff = (uint32_t)((wn * 32 + (lid & 7) + (lid >> 4) * 8) * ASTR
                               + ((lid >> 3) & 1) * 8) * 2;

    float acc[2][4][4];
    #pragma unroll
    for (int i = 0; i < 2; i++)
        #pragma unroll
        for (int j = 0; j < 4; j++)
            #pragma unroll
            for (int r = 0; r < 4; r++) acc[i][j][r] = 0.f;

    int np = w1tile ? 3 : 1;

    ld_tile(sbase + OFF_AHI(0), Ah, 128, tid);
    ld_tile(sbase + OFF_BHI(0), Bh, 64, tid);
    if (w1tile) {
        ld_tile(sbase + OFF_ALO(0), Al, 128, tid);
        ld_tile(sbase + OFF_BLO(0), Bl, 64, tid);
    }
    CP_COMMIT();

    for (int s = 0; s < NSTAGE; s++) {
        int buf = s & 1;
        if (s + 1 < NSTAGE) {
            int nb = buf ^ 1;
            ld_tile(sbase + OFF_AHI(nb), Ah + (s + 1) * BK, 128, tid);
            ld_tile(sbase + OFF_BHI(nb), Bh + (s + 1) * BK, 64, tid);
            if (w1tile) {
                ld_tile(sbase + OFF_ALO(nb), Al + (s + 1) * BK, 128, tid);
                ld_tile(sbase + OFF_BLO(nb), Bl + (s + 1) * BK, 64, tid);
            }
            CP_COMMIT();
            cp_wait<1>();
        } else {
            cp_wait<0>();
        }
        __syncthreads();

        for (int p = 0; p < np; p++) {
            uint32_t Asm = sbase + ((p == 2) ? OFF_ALO(buf) : OFF_AHI(buf));
            uint32_t Bsm = sbase + ((p == 1) ? OFF_BLO(buf) : OFF_BHI(buf));
            #pragma unroll
            for (int kk = 0; kk < BK; kk += 16) {
                uint32_t af[2][4], bfm[2][4];
                ldsm_x4(af[0],  Asm + aoff + kk * 2);
                ldsm_x4(af[1],  Asm + aoff + 16 * ASTR * 2 + kk * 2);
                ldsm_x4(bfm[0], Bsm + boff + kk * 2);
                ldsm_x4(bfm[1], Bsm + boff + 16 * ASTR * 2 + kk * 2);
                #pragma unroll
                for (int mi = 0; mi < 2; mi++)
                    #pragma unroll
                    for (int ni = 0; ni < 4; ni++)
                        mma16816(acc[mi][ni], af[mi], &bfm[ni >> 1][(ni & 1) * 2]);
            }
        }
        __syncthreads();
    }

    float* Eout = g_E + (size_t)ks * NF * NCOL;
    #pragma unroll
    for (int mi = 0; mi < 2; mi++) {
        #pragma unroll
        for (int ni = 0; ni < 4; ni++) {
            int r0 = bm + wm * 32 + mi * 16 + g;
            int c  = bn + wn * 32 + ni * 8 + 2 * t;
            *(float2*)&Eout[(size_t)r0 * NCOL + c]       = make_float2(acc[mi][ni][0], acc[mi][ni][1]);
            *(float2*)&Eout[(size_t)(r0 + 8) * NCOL + c] = make_float2(acc[mi][ni][2], acc[mi][ni][3]);
        }
    }
}

// ---------------- 4) gates + f2f bitmask -----------------------------------------
__global__ void __launch_bounds__(128) k_gates(const float* __restrict__ b1,
                                               const float* __restrict__ W2,
                                               const float* __restrict__ b2) {
    __shared__ float sh[4];
    int f   = blockIdx.x;
    int tid = threadIdx.x;
    const size_t P = (size_t)NF * NCOL;

    float s = 0.f;
    #pragma unroll
    for (int h = tid; h < HID; h += 128) {
        size_t idx = (size_t)f * NCOL + h;
        float v = g_E[idx] + g_E[idx + P] + g_E[idx + 2 * P] + g_E[idx + 3 * P]
                + g_tvec[h] + b1[h];
        s += fmaxf(v, 0.f) * W2[h];
    }
    float tot = block_sum<4>(s, sh);
    if (tid == 0) g_gates[f] = 1.0f / (1.0f + expf(-(tot + b2[0])));

    float invi = g_inv[f];
    #pragma unroll
    for (int j = tid; j < NF; j += 128) {
        size_t idx = (size_t)f * NCOL + HID + j;
        float d = g_E[idx] + g_E[idx + P] + g_E[idx + 2 * P] + g_E[idx + 3 * P];
        float c = d * invi * g_inv[j];
        unsigned bal = __ballot_sync(0xffffffffu, c > 0.98f);
        if ((j & 31) == 0) g_mask[f * 16 + (j >> 5)] = bal;
    }
}

// ---------------- 5) greedy selection (warp-shuffle argmax) -----------------------
__global__ void __launch_bounds__(512) k_select(float* __restrict__ out, int out_size) {
    __shared__ float    sg[NF];
    __shared__ unsigned svis[16];
    __shared__ int      ssel[NF];
    __shared__ float    wv[16];
    __shared__ int      wi2[16];
    __shared__ int      scur;
    __shared__ float    sbest;
    int tid = threadIdx.x, lid = tid & 31, wid = tid >> 5;
    sg[tid]   = g_gates[tid];
    ssel[tid] = 0;
    if (tid < 16) svis[tid] = 0u;
    __syncthreads();

    for (int it = 0; it < 32; it++) {
        float v = ((svis[wid] >> lid) & 1u) ? -1e30f : sg[tid];
        int   i = tid;
        #pragma unroll
        for (int o = 16; o > 0; o >>= 1) {
            float vo = __shfl_down_sync(0xffffffffu, v, o);
            int   io = __shfl_down_sync(0xffffffffu, i, o);
            if (vo > v || (vo == v && io < i)) { v = vo; i = io; }
        }
        if (lid == 0) { wv[wid] = v; wi2[wid] = i; }
        __syncthreads();
        if (wid == 0) {
            float v2 = (lid < 16) ? wv[lid]  : -1e30f;
            int   i2 = (lid < 16) ? wi2[lid] : 0x7fffffff;
            #pragma unroll
            for (int o = 8; o > 0; o >>= 1) {
                float vo = __shfl_down_sync(0xffffffffu, v2, o);
                int   io = __shfl_down_sync(0xffffffffu, i2, o);
                if (vo > v2 || (vo == v2 && io < i2)) { v2 = vo; i2 = io; }
            }
            if (lid == 0) { scur = i2; sbest = v2; }
        }
        __syncthreads();
        if (sbest < -1e29f) break;
        int cur = scur;
        if (tid == 0)  ssel[cur] = 1;
        if (tid < 16)  svis[tid] |= g_mask[cur * 16 + tid];
        __syncthreads();
    }

    if (tid < out_size)      out[tid]      = (float)ssel[tid];
    if (NF + tid < out_size) out[NF + tid] = sg[tid];
}

// ---------------- launch -----------------------------------------------------------
extern "C" void kernel_launch(void* const* d_in, const int* in_sizes, int n_in,
                              void* d_out, int out_size) {
    const float* img    = (const float*)d_in[0];
    const float* txt    = (const float*)d_in[1];
    const float* ln_t_g = (const float*)d_in[2];
    const float* ln_t_b = (const float*)d_in[3];
    const float* ln_l_g = (const float*)d_in[4];
    const float* ln_l_b = (const float*)d_in[5];
    const float* W1     = (const float*)d_in[6];
    const float* b1     = (const float*)d_in[7];
    const float* W2     = (const float*)d_in[8];
    const float* b2     = (const float*)d_in[9];
    float* out = (float*)d_out;

    cudaFuncSetAttribute(k_gemm_mma, cudaFuncAttributeMaxDynamicSharedMemorySize, SM_TOT);

    k_meanln<<<NF + 1, 512>>>(img, txt, ln_l_g, ln_l_b, ln_t_g, ln_t_b);
    k_wconv<<<dim3(EMB / 32, HID / 32), dim3(32, 8)>>>(W1);
    k_tvec<<<EMB / 16, 512>>>(W1);
    k_gemm_mma<<<dim3(NCOL / 64, NF / 128, KSPLIT), 256, SM_TOT>>>();
    k_gates<<<NF, 128>>>(b1, W2, b2);
    k_select<<<1, 512>>>(out, out_size);
}

// round 7
// speedup vs baseline: 2.5661x; 1.1009x over previous
#include <cuda_runtime.h>
#include <cuda_bf16.h>
#include <math.h>
#include <stdint.h>

#define NF   512
#define TOK  196
#define EMB  2560
#define HID  512
#define NCOL (HID + NF)          // 1024
#define KSPLIT 4
#define KCHUNK (EMB / KSPLIT)    // 640
#define BK 32
#define NSTAGE (KCHUNK / BK)     // 20
#define ASTR 40                  // smem row stride in bf16 (32 + 8 pad)

// ---------------- scratch (device globals) ----------------------------------
__device__ __nv_bfloat16 g_Ahi[NF * EMB];      // layernormed pooled, bf16 hi
__device__ __nv_bfloat16 g_Alo[NF * EMB];      // residual lo
__device__ __nv_bfloat16 g_Whi[HID * EMB];     // W1_bot^T bf16 hi  [n][k]
__device__ __nv_bfloat16 g_Wlo[HID * EMB];     // W1_bot^T residual lo
__device__ float         g_txt[EMB];
__device__ float         g_inv[NF];
__device__ float         g_tvec[HID];
__device__ float         g_E[KSPLIT * NF * NCOL];
__device__ float         g_gates[NF];
__device__ unsigned      g_mask[NF * 16];

// ---------------- PTX helpers -------------------------------------------------
__device__ __forceinline__ uint32_t smem_u32(const void* p) {
    uint32_t a;
    asm("{ .reg .u64 t; cvta.to.shared.u64 t, %1; cvt.u32.u64 %0, t; }" : "=r"(a) : "l"(p));
    return a;
}
__device__ __forceinline__ void cpa16(uint32_t d, const void* s) {
    asm volatile("cp.async.cg.shared.global [%0], [%1], 16;" :: "r"(d), "l"(s));
}
#define CP_COMMIT() asm volatile("cp.async.commit_group;" ::: "memory")
template<int N>
__device__ __forceinline__ void cp_wait() {
    asm volatile("cp.async.wait_group %0;" :: "n"(N) : "memory");
}
__device__ __forceinline__ void mma16816(float* d, const uint32_t* a, const uint32_t* b) {
    asm volatile(
        "mma.sync.aligned.m16n8k16.row.col.f32.bf16.bf16.f32 "
        "{%0,%1,%2,%3}, {%4,%5,%6,%7}, {%8,%9}, {%0,%1,%2,%3};"
        : "+f"(d[0]), "+f"(d[1]), "+f"(d[2]), "+f"(d[3])
        : "r"(a[0]), "r"(a[1]), "r"(a[2]), "r"(a[3]), "r"(b[0]), "r"(b[1]));
}
__device__ __forceinline__ void ldsm_x4(uint32_t* r, uint32_t addr) {
    asm volatile("ldmatrix.sync.aligned.m8n8.x4.shared.b16 {%0,%1,%2,%3}, [%4];"
        : "=r"(r[0]), "=r"(r[1]), "=r"(r[2]), "=r"(r[3]) : "r"(addr));
}

// ---------------- helpers ------------------------------------------------------
template<int NW>
__device__ __forceinline__ float block_sum(float v, float* sh) {
    #pragma unroll
    for (int o = 16; o > 0; o >>= 1) v += __shfl_down_sync(0xffffffffu, v, o);
    if ((threadIdx.x & 31) == 0) sh[threadIdx.x >> 5] = v;
    __syncthreads();
    float tot = 0.f;
    #pragma unroll
    for (int i = 0; i < NW; i++) tot += sh[i];
    __syncthreads();
    return tot;
}

// ---------------- 1) fused token-mean + layernorm (vectorized) -------------------
// Each thread owns e = 4*tid..4*tid+3 (float4) and e = 2048+tid (scalar).
// blocks 0..NF-1: frame rows; block NF: text row (also zeroes g_tvec)
__global__ void __launch_bounds__(512) k_meanln(const float* __restrict__ img,
                                                const float* __restrict__ txt,
                                                const float* __restrict__ lng,
                                                const float* __restrict__ lnb,
                                                const float* __restrict__ tg,
                                                const float* __restrict__ tb) {
    __shared__ float sh[16];
    int  f     = blockIdx.x;
    bool istxt = (f == NF);
    int  tid   = threadIdx.x;

    float4 v4;
    float  v1;
    if (istxt) {
        g_tvec[tid] = 0.f;
        v4 = reinterpret_cast<const float4*>(txt)[tid];
        v1 = txt[2048 + tid];
    } else {
        const float4* p4 = reinterpret_cast<const float4*>(img + (size_t)f * TOK * EMB);
        const float*  p1 = img + (size_t)f * TOK * EMB + 2048 + tid;
        float4 a4 = make_float4(0.f, 0.f, 0.f, 0.f);
        float  a1 = 0.f;
        #pragma unroll 4
        for (int t = 0; t < TOK; t++) {
            float4 x = p4[(size_t)t * 640 + tid];
            a4.x += x.x; a4.y += x.y; a4.z += x.z; a4.w += x.w;
            a1 += p1[(size_t)t * EMB];
        }
        const float s = 1.0f / (float)TOK;
        v4 = make_float4(a4.x * s, a4.y * s, a4.z * s, a4.w * s);
        v1 = a1 * s;
    }

    const float* gam = istxt ? tg : lng;
    const float* bet = istxt ? tb : lnb;
    float s  = v4.x + v4.y + v4.z + v4.w + v1;
    float s2 = v4.x * v4.x + v4.y * v4.y + v4.z * v4.z + v4.w * v4.w + v1 * v1;
    float S  = block_sum<16>(s,  sh);
    float S2 = block_sum<16>(s2, sh);
    float mean = S * (1.0f / EMB);
    float var  = S2 * (1.0f / EMB) - mean * mean;
    float rstd = rsqrtf(var + 1e-5f);

    float vv[5] = {v4.x, v4.y, v4.z, v4.w, v1};
    int   ee[5] = {4 * tid, 4 * tid + 1, 4 * tid + 2, 4 * tid + 3, 2048 + tid};
    float y[5];
    float n2 = 0.f;
    #pragma unroll
    for (int i = 0; i < 5; i++) {
        y[i] = (vv[i] - mean) * rstd * gam[ee[i]] + bet[ee[i]];
        n2 += y[i] * y[i];
    }
    if (istxt) {
        #pragma unroll
        for (int i = 0; i < 5; i++) g_txt[ee[i]] = y[i];
    } else {
        __nv_bfloat16 hi[5];
        #pragma unroll
        for (int i = 0; i < 5; i++) hi[i] = __float2bfloat16(y[i]);
        // vector part: 4 bf16 = 8 bytes
        __nv_bfloat16* dsth = g_Ahi + (size_t)f * EMB;
        __nv_bfloat16* dstl = g_Alo + (size_t)f * EMB;
        __nv_bfloat16 hv[4] = {hi[0], hi[1], hi[2], hi[3]};
        *reinterpret_cast<uint2*>(dsth + 4 * tid) = *reinterpret_cast<uint2*>(hv);
        __nv_bfloat16 lv[4];
        #pragma unroll
        for (int i = 0; i < 4; i++) lv[i] = __float2bfloat16(y[i] - __bfloat162float(hi[i]));
        *reinterpret_cast<uint2*>(dstl + 4 * tid) = *reinterpret_cast<uint2*>(lv);
        dsth[2048 + tid] = hi[4];
        dstl[2048 + tid] = __float2bfloat16(y[4] - __bfloat162float(hi[4]));
        float N2 = block_sum<16>(n2, sh);
        if (tid == 0) g_inv[f] = 1.0f / fmaxf(sqrtf(N2), 1e-8f);
    }
}

// ---------------- 2) W1_bot -> transposed bf16 hi/lo [n][k] ---------------------
__global__ void __launch_bounds__(256) k_wconv(const float* __restrict__ W1) {
    __shared__ float t[32][33];
    const float* Wb = W1 + (size_t)EMB * HID;
    int k0 = blockIdx.x * 32, n0 = blockIdx.y * 32;
    int tx = threadIdx.x, ty = threadIdx.y;
    #pragma unroll
    for (int j = ty; j < 32; j += 8)
        t[j][tx] = Wb[(size_t)(k0 + j) * HID + n0 + tx];
    __syncthreads();
    #pragma unroll
    for (int j = ty; j < 32; j += 8) {
        float x = t[tx][j];
        __nv_bfloat16 hi = __float2bfloat16(x);
        g_Whi[(size_t)(n0 + j) * EMB + k0 + tx] = hi;
        g_Wlo[(size_t)(n0 + j) * EMB + k0 + tx] = __float2bfloat16(x - __bfloat162float(hi));
    }
}

// ---------------- 2b) tvec = txt_ln @ W1_top ------------------------------------
__global__ void __launch_bounds__(512) k_tvec(const float* __restrict__ W1) {
    int h  = threadIdx.x;
    int e0 = blockIdx.x * 16;
    __shared__ float st[16];
    if (threadIdx.x < 16) st[threadIdx.x] = g_txt[e0 + threadIdx.x];
    __syncthreads();
    float s = 0.f;
    const float* w = W1 + (size_t)e0 * HID + h;
    #pragma unroll
    for (int e = 0; e < 16; e++) s = fmaf(st[e], w[(size_t)e * HID], s);
    atomicAdd(&g_tvec[h], s);
}

// ---------------- 3) HMMA GEMM, 3-stage cp.async pipeline ------------------------
#define STG_SZ  30720                    // bytes per stage: Ahi+Alo (2*10240) + Bhi+Blo (2*5120)
#define OFF_AHI(b) ((b) * STG_SZ)
#define OFF_ALO(b) ((b) * STG_SZ + 10240)
#define OFF_BHI(b) ((b) * STG_SZ + 20480)
#define OFF_BLO(b) ((b) * STG_SZ + 25600)
#define SM_TOT (3 * STG_SZ)              // 92160

__device__ __forceinline__ void ld_tile(uint32_t sm, const __nv_bfloat16* g,
                                        int rows, int tid) {
    int nvec = rows * 4;
    for (int i = tid; i < nvec; i += 256) {
        int row = i >> 2, seg = i & 3;
        cpa16(sm + (uint32_t)(row * ASTR + seg * 8) * 2,
              g + (size_t)row * EMB + seg * 8);
    }
}

__global__ void __launch_bounds__(256, 2) k_gemm_mma() {
    extern __shared__ char smem[];
    uint32_t sbase = smem_u32(smem);
    int tid = threadIdx.x, wid = tid >> 5, lid = tid & 31;
    int bn = blockIdx.x * 64, bm = blockIdx.y * 128, ks = blockIdx.z;
    int kb = ks * KCHUNK;
    bool w1tile = (bn < HID);

    const __nv_bfloat16* Ah = g_Ahi + (size_t)bm * EMB + kb;
    const __nv_bfloat16* Al = g_Alo + (size_t)bm * EMB + kb;
    const __nv_bfloat16* Bh = w1tile ? (g_Whi + (size_t)bn * EMB + kb)
                                     : (g_Ahi + (size_t)(bn - HID) * EMB + kb);
    const __nv_bfloat16* Bl = g_Wlo + (size_t)bn * EMB + kb;   // W1 tiles only

    int wm = wid & 3;            // 4 warp rows * 32 = 128
    int wn = wid >> 2;           // 2 warp cols * 32 = 64
    int g  = lid >> 2;           // 0..7
    int t  = lid & 3;            // 0..3

    uint32_t aoff = (uint32_t)((wm * 32 + (lid & 15)) * ASTR + (lid >> 4) * 8) * 2;
    uint32_t boff = (uint32_t)((wn * 32 + (lid & 7) + (lid >> 4) * 8) * ASTR
                               + ((lid >> 3) & 1) * 8) * 2;

    float acc[2][4][4];
    #pragma unroll
    for (int i = 0; i < 2; i++)
        #pragma unroll
        for (int j = 0; j < 4; j++)
            #pragma unroll
            for (int r = 0; r < 4; r++) acc[i][j][r] = 0.f;

    int np = w1tile ? 3 : 1;

    // prologue: stages 0,1
    #pragma unroll
    for (int s = 0; s < 2; s++) {
        ld_tile(sbase + OFF_AHI(s), Ah + s * BK, 128, tid);
        ld_tile(sbase + OFF_BHI(s), Bh + s * BK, 64, tid);
        if (w1tile) {
            ld_tile(sbase + OFF_ALO(s), Al + s * BK, 128, tid);
            ld_tile(sbase + OFF_BLO(s), Bl + s * BK, 64, tid);
        }
        CP_COMMIT();
    }

    for (int s = 0; s < NSTAGE; s++) {
        int buf = s % 3;
        if (s + 2 < NSTAGE) {
            int nb = (s + 2) % 3;
            ld_tile(sbase + OFF_AHI(nb), Ah + (s + 2) * BK, 128, tid);
            ld_tile(sbase + OFF_BHI(nb), Bh + (s + 2) * BK, 64, tid);
            if (w1tile) {
                ld_tile(sbase + OFF_ALO(nb), Al + (s + 2) * BK, 128, tid);
                ld_tile(sbase + OFF_BLO(nb), Bl + (s + 2) * BK, 64, tid);
            }
            CP_COMMIT();
            cp_wait<2>();
        } else if (s + 1 < NSTAGE) {
            cp_wait<1>();
        } else {
            cp_wait<0>();
        }
        __syncthreads();

        for (int p = 0; p < np; p++) {
            uint32_t Asm = sbase + ((p == 2) ? OFF_ALO(buf) : OFF_AHI(buf));
            uint32_t Bsm = sbase + ((p == 1) ? OFF_BLO(buf) : OFF_BHI(buf));
            #pragma unroll
            for (int kk = 0; kk < BK; kk += 16) {
                uint32_t af[2][4], bfm[2][4];
                ldsm_x4(af[0],  Asm + aoff + kk * 2);
                ldsm_x4(af[1],  Asm + aoff + 16 * ASTR * 2 + kk * 2);
                ldsm_x4(bfm[0], Bsm + boff + kk * 2);
                ldsm_x4(bfm[1], Bsm + boff + 16 * ASTR * 2 + kk * 2);
                #pragma unroll
                for (int mi = 0; mi < 2; mi++)
                    #pragma unroll
                    for (int ni = 0; ni < 4; ni++)
                        mma16816(acc[mi][ni], af[mi], &bfm[ni >> 1][(ni & 1) * 2]);
            }
        }
        __syncthreads();
    }

    float* Eout = g_E + (size_t)ks * NF * NCOL;
    #pragma unroll
    for (int mi = 0; mi < 2; mi++) {
        #pragma unroll
        for (int ni = 0; ni < 4; ni++) {
            int r0 = bm + wm * 32 + mi * 16 + g;
            int c  = bn + wn * 32 + ni * 8 + 2 * t;
            *(float2*)&Eout[(size_t)r0 * NCOL + c]       = make_float2(acc[mi][ni][0], acc[mi][ni][1]);
            *(float2*)&Eout[(size_t)(r0 + 8) * NCOL + c] = make_float2(acc[mi][ni][2], acc[mi][ni][3]);
        }
    }
}

// ---------------- 4) gates + f2f bitmask -----------------------------------------
__global__ void __launch_bounds__(128) k_gates(const float* __restrict__ b1,
                                               const float* __restrict__ W2,
                                               const float* __restrict__ b2) {
    __shared__ float sh[4];
    int f   = blockIdx.x;
    int tid = threadIdx.x;
    const size_t P = (size_t)NF * NCOL;

    float s = 0.f;
    #pragma unroll
    for (int h = tid; h < HID; h += 128) {
        size_t idx = (size_t)f * NCOL + h;
        float v = g_E[idx] + g_E[idx + P] + g_E[idx + 2 * P] + g_E[idx + 3 * P]
                + g_tvec[h] + b1[h];
        s += fmaxf(v, 0.f) * W2[h];
    }
    float tot = block_sum<4>(s, sh);
    if (tid == 0) g_gates[f] = 1.0f / (1.0f + expf(-(tot + b2[0])));

    float invi = g_inv[f];
    #pragma unroll
    for (int j = tid; j < NF; j += 128) {
        size_t idx = (size_t)f * NCOL + HID + j;
        float d = g_E[idx] + g_E[idx + P] + g_E[idx + 2 * P] + g_E[idx + 3 * P];
        float c = d * invi * g_inv[j];
        unsigned bal = __ballot_sync(0xffffffffu, c > 0.98f);
        if ((j & 31) == 0) g_mask[f * 16 + (j >> 5)] = bal;
    }
}

// ---------------- 5) greedy selection (warp-shuffle argmax) -----------------------
__global__ void __launch_bounds__(512) k_select(float* __restrict__ out, int out_size) {
    __shared__ float    sg[NF];
    __shared__ unsigned svis[16];
    __shared__ int      ssel[NF];
    __shared__ float    wv[16];
    __shared__ int      wi2[16];
    __shared__ int      scur;
    __shared__ float    sbest;
    int tid = threadIdx.x, lid = tid & 31, wid = tid >> 5;
    sg[tid]   = g_gates[tid];
    ssel[tid] = 0;
    if (tid < 16) svis[tid] = 0u;
    __syncthreads();

    for (int it = 0; it < 32; it++) {
        float v = ((svis[wid] >> lid) & 1u) ? -1e30f : sg[tid];
        int   i = tid;
        #pragma unroll
        for (int o = 16; o > 0; o >>= 1) {
            float vo = __shfl_down_sync(0xffffffffu, v, o);
            int   io = __shfl_down_sync(0xffffffffu, i, o);
            if (vo > v || (vo == v && io < i)) { v = vo; i = io; }
        }
        if (lid == 0) { wv[wid] = v; wi2[wid] = i; }
        __syncthreads();
        if (wid == 0) {
            float v2 = (lid < 16) ? wv[lid]  : -1e30f;
            int   i2 = (lid < 16) ? wi2[lid] : 0x7fffffff;
            #pragma unroll
            for (int o = 8; o > 0; o >>= 1) {
                float vo = __shfl_down_sync(0xffffffffu, v2, o);
                int   io = __shfl_down_sync(0xffffffffu, i2, o);
                if (vo > v2 || (vo == v2 && io < i2)) { v2 = vo; i2 = io; }
            }
            if (lid == 0) { scur = i2; sbest = v2; }
        }
        __syncthreads();
        if (sbest < -1e29f) break;
        int cur = scur;
        if (tid == 0)  ssel[cur] = 1;
        if (tid < 16)  svis[tid] |= g_mask[cur * 16 + tid];
        __syncthreads();
    }

    if (tid < out_size)      out[tid]      = (float)ssel[tid];
    if (NF + tid < out_size) out[NF + tid] = sg[tid];
}

// ---------------- launch -----------------------------------------------------------
extern "C" void kernel_launch(void* const* d_in, const int* in_sizes, int n_in,
                              void* d_out, int out_size) {
    const float* img    = (const float*)d_in[0];
    const float* txt    = (const float*)d_in[1];
    const float* ln_t_g = (const float*)d_in[2];
    const float* ln_t_b = (const float*)d_in[3];
    const float* ln_l_g = (const float*)d_in[4];
    const float* ln_l_b = (const float*)d_in[5];
    const float* W1     = (const float*)d_in[6];
    const float* b1     = (const float*)d_in[7];
    const float* W2     = (const float*)d_in[8];
    const float* b2     = (const float*)d_in[9];
    float* out = (float*)d_out;

    cudaFuncSetAttribute(k_gemm_mma, cudaFuncAttributeMaxDynamicSharedMemorySize, SM_TOT);

    k_meanln<<<NF + 1, 512>>>(img, txt, ln_l_g, ln_l_b, ln_t_g, ln_t_b);
    k_wconv<<<dim3(EMB / 32, HID / 32), dim3(32, 8)>>>(W1);
    k_tvec<<<EMB / 16, 512>>>(W1);
    k_gemm_mma<<<dim3(NCOL / 64, NF / 128, KSPLIT), 256, SM_TOT>>>();
    k_gates<<<NF, 128>>>(b1, W2, b2);
    k_select<<<1, 512>>>(out, out_size);
}